// round 17
// baseline (speedup 1.0000x reference)
#include <cuda_runtime.h>
#include <cuda_fp16.h>
#include <cstdint>

#define BATCH 4096
#define MCOLS 4096
#define NROWS 4096
#define NNZ_PER_ROW 819
#define NNZ_TOTAL (NROWS * NNZ_PER_ROW)

#define BM 128
#define BN 128
#define BK 32
#define KSTEPS (MCOLS / BK)        // 128 ktiles -> 64 two-ktile steps
#define NSTAGES 6
#define TILE_BYTES 8192            // 128 rows x 64B (32 halves), swizzled, no padding
#define STAGE_BYTES (2 * TILE_BYTES)             // A+B (16KB)
#define SMEM_BYTES (NSTAGES * STAGE_BYTES)       // 98304 B -> 2 CTAs/SM

#define XCHUNKS (BATCH * MCOLS / 4)   // float4 chunks of x

// fp16 operand buffers. g_Wh is zero-initialized at module load (0 bits = +0.0h);
// the prep kernel writes the same values to the same (fixed CSR) positions every
// call -> deterministic across graph replays.
__device__ __half g_Wh[(size_t)NROWS * MCOLS];
__device__ __half g_Xh[(size_t)BATCH * MCOLS];

__global__ void __launch_bounds__(256)
prep_kernel(const float* __restrict__ x, const float* __restrict__ val,
            const int* __restrict__ rows, const int* __restrict__ cols) {
    int i = blockIdx.x * blockDim.x + threadIdx.x;
    if (i < XCHUNKS) {
        size_t o = (size_t)i * 4;
        float4 v = *(const float4*)(x + o);
        __half2 h0 = __floats2half2_rn(v.x, v.y);
        __half2 h1 = __floats2half2_rn(v.z, v.w);
        uint2 p;
        p.x = *(const uint32_t*)&h0;
        p.y = *(const uint32_t*)&h1;
        *(uint2*)(g_Xh + o) = p;
    } else {
        int j = i - XCHUNKS;
        if (j < NNZ_TOTAL) {
            g_Wh[(size_t)rows[j] * MCOLS + cols[j]] = __float2half_rn(val[j]);
        }
    }
}

__device__ __forceinline__ void cp16(uint32_t dst, const void* src) {
    asm volatile("cp.async.cg.shared.global [%0], [%1], 16;\n" :: "r"(dst), "l"(src));
}

// Swizzled stage loader. Thread owns (row tid>>1, 32B half-row tid&1).
__device__ __forceinline__ void load_stage(uint32_t w0, uint32_t w1, uint32_t so,
                                           const __half* __restrict__ gA,
                                           const __half* __restrict__ gB) {
    cp16(w0 + so, gA);
    cp16(w1 + so, gA + 8);
    cp16(w0 + so + TILE_BYTES, gB);
    cp16(w1 + so + TILE_BYTES, gB + 8);
    asm volatile("cp.async.commit_group;\n" ::);
}

#define MMA(d, a0, a1, a2, a3, b0, b1)                                      \
    asm volatile(                                                           \
        "mma.sync.aligned.m16n8k16.row.col.f32.f16.f16.f32 "                \
        "{%0,%1,%2,%3}, {%4,%5,%6,%7}, {%8,%9}, {%0,%1,%2,%3};"             \
        : "+f"((d)[0]), "+f"((d)[1]), "+f"((d)[2]), "+f"((d)[3])            \
        : "r"(a0), "r"(a1), "r"(a2), "r"(a3), "r"(b0), "r"(b1))

#define LDSM4(r0, r1, r2, r3, addr)                                         \
    asm volatile("ldmatrix.sync.aligned.m8n8.x4.shared.b16 "                \
                 "{%0,%1,%2,%3}, [%4];"                                     \
                 : "=r"(r0), "=r"(r1), "=r"(r2), "=r"(r3) : "r"(addr))

__device__ __forceinline__ void ldsm_a(uint32_t afc[2][4], uint32_t aBase, uint32_t offA) {
    LDSM4(afc[0][0], afc[0][1], afc[0][2], afc[0][3], aBase + offA);
    LDSM4(afc[1][0], afc[1][1], afc[1][2], afc[1][3], aBase + 1024 + offA);
}
__device__ __forceinline__ void ldsm_b2(uint32_t bfc[8][2], uint32_t bBase,
                                        uint32_t offB, int ntp) {
    LDSM4(bfc[2 * ntp][0], bfc[2 * ntp][1], bfc[2 * ntp + 1][0], bfc[2 * ntp + 1][1],
          bBase + (uint32_t)(ntp * 1024) + offB);
    LDSM4(bfc[2 * ntp + 2][0], bfc[2 * ntp + 2][1], bfc[2 * ntp + 3][0], bfc[2 * ntp + 3][1],
          bBase + (uint32_t)((ntp + 1) * 1024) + offB);
}

__device__ __forceinline__ void mma_quad(float accm[8][4], const uint32_t a[4],
                                         const uint32_t bfc[8][2], int nb) {
    #pragma unroll
    for (int j = 0; j < 4; ++j)
        MMA(accm[nb + j], a[0], a[1], a[2], a[3], bfc[nb + j][0], bfc[nb + j][1]);
}

// One ks-step of MMAs (16) with the NEXT fragment load's 6 LDSMs woven between
// the quads, so LDSM latency hides under tensor execution.
__device__ __forceinline__ void mma_phase(float acc[2][8][4],
                                          const uint32_t afc[2][4],
                                          const uint32_t bfc[8][2],
                                          uint32_t afn[2][4], uint32_t bfn[8][2],
                                          uint32_t aLd, uint32_t bLd,
                                          uint32_t offALd, uint32_t offBLd) {
    mma_quad(acc[0], afc[0], bfc, 0);
    ldsm_a(afn, aLd, offALd);
    mma_quad(acc[0], afc[0], bfc, 4);
    ldsm_b2(bfn, bLd, offBLd, 0);
    mma_quad(acc[1], afc[1], bfc, 0);
    ldsm_b2(bfn, bLd, offBLd, 2);
    mma_quad(acc[1], afc[1], bfc, 4);
}

__device__ __forceinline__ uint32_t wrap6(uint32_t so) {
    return (so >= (uint32_t)SMEM_BYTES) ? so - (uint32_t)SMEM_BYTES : so;
}

__global__ void __launch_bounds__(256, 2)
sgemm_fp16(const float* __restrict__ bias, float* __restrict__ out) {
    extern __shared__ __half smem[];

    const int tid  = threadIdx.x;
    const int lane = tid & 31;
    const int warp = tid >> 5;
    const int wm = (warp & 3) * 32;     // 4 warps in M
    const int wn = (warp >> 2) * 64;    // 2 warps in N
    const int qr = lane >> 2;
    const int tg = lane & 3;

    const int m0 = blockIdx.y * BM;
    const int n0 = blockIdx.x * BN;

    float acc[2][8][4];
    #pragma unroll
    for (int i = 0; i < 2; i++)
        #pragma unroll
        for (int j = 0; j < 8; j++)
            #pragma unroll
            for (int c = 0; c < 4; c++) acc[i][j][c] = 0.f;

    const uint32_t sbase = (uint32_t)__cvta_generic_to_shared(smem);

    // ldmatrix per-lane bases + swizzled chunk offsets (R16 mapping)
    const int rA = wm + (lane & 7) + ((lane >> 3) & 1) * 8;
    const int clA = lane >> 4;
    const int rB = wn + (lane & 7) + ((lane >> 4) & 1) * 8;
    const int clB = (lane >> 3) & 1;
    const uint32_t qA = (uint32_t)((rA >> 1) & 3);
    const uint32_t qB = (uint32_t)((rB >> 1) & 3);
    const uint32_t aLane = sbase + (uint32_t)(rA * 64);
    const uint32_t bLane = sbase + (uint32_t)TILE_BYTES + (uint32_t)(rB * 64);
    const uint32_t offA0 = (((uint32_t)clA ^ qA) << 4);
    const uint32_t offA1 = (((uint32_t)(2 + clA) ^ qA) << 4);
    const uint32_t offB0 = (((uint32_t)clB ^ qB) << 4);
    const uint32_t offB1 = (((uint32_t)(2 + clB) ^ qB) << 4);

    // loader thread's (row, half-row) and swizzled write offsets
    const int lrow = tid >> 1;
    const int lh = tid & 1;
    const uint32_t lq = (uint32_t)((lrow >> 1) & 3);
    const uint32_t w0 = sbase + (uint32_t)(lrow * 64)
                      + ((((uint32_t)(2 * lh)) ^ lq) << 4);
    const uint32_t w1 = sbase + (uint32_t)(lrow * 64)
                      + ((((uint32_t)(2 * lh + 1)) ^ lq) << 4);
    const __half* gA = g_Xh + (size_t)(m0 + lrow) * MCOLS + lh * 16;
    const __half* gB = g_Wh + (size_t)(n0 + lrow) * MCOLS + lh * 16;

    // prologue: stages 0..3; complete 0,1,2 (pending: 3)
    load_stage(w0, w1, 0 * STAGE_BYTES, gA, gB);
    load_stage(w0, w1, 1 * STAGE_BYTES, gA + BK, gB + BK);
    load_stage(w0, w1, 2 * STAGE_BYTES, gA + 2 * BK, gB + 2 * BK);
    load_stage(w0, w1, 3 * STAGE_BYTES, gA + 3 * BK, gB + 3 * BK);
    asm volatile("cp.async.wait_group 1;\n" ::);
    __syncthreads();

    uint32_t af[2][2][4];
    uint32_t bf[2][8][2];
    // one-time preload (ktile 0, ks0)
    ldsm_a(af[0], aLane, offA0);
    ldsm_b2(bf[0], bLane, offB0, 0);
    ldsm_b2(bf[0], bLane, offB0, 2);

    uint32_t sb0 = 0;   // byte offset of the stage holding ktile e
    for (int s = 0; s < KSTEPS / 2; ++s) {
        const int e = 2 * s;
        const uint32_t s0 = sb0;
        const uint32_t s1 = wrap6(sb0 + STAGE_BYTES);
        const uint32_t s2 = wrap6(sb0 + 2 * STAGE_BYTES);
        const uint32_t s4 = wrap6(sb0 + 4 * STAGE_BYTES);
        const uint32_t s5 = wrap6(sb0 + 5 * STAGE_BYTES);

        // ktile e ks0 MMAs + woven LDSM of (e, ks1)
        mma_phase(acc, af[0], bf[0], af[1], bf[1],
                  aLane + s0, bLane + s0, offA1, offB1);

        // prefetch stage e+4 into buffer (e+4)%6 == (e-2)%6 (read-complete
        // since the previous step's exit barrier).
        if (e + 4 < KSTEPS)
            load_stage(w0, w1, s4, gA + (size_t)(e + 4) * BK, gB + (size_t)(e + 4) * BK);

        // ktile e ks1 MMAs + woven LDSM of (e+1, ks0)
        mma_phase(acc, af[1], bf[1], af[0], bf[0],
                  aLane + s1, bLane + s1, offA0, offB0);

        // prefetch stage e+5 into buffer (e+5)%6 == (e-1)%6
        if (e + 5 < KSTEPS)
            load_stage(w0, w1, s5, gA + (size_t)(e + 5) * BK, gB + (size_t)(e + 5) * BK);

        // ktile e+1 ks0 MMAs + woven LDSM of (e+1, ks1)
        mma_phase(acc, af[0], bf[0], af[1], bf[1],
                  aLane + s1, bLane + s1, offA1, offB1);

        // ktile e+1 ks1 MMAs + woven preload of (e+2, ks0) from stage e+2:
        // complete since this step's entry barrier, not a prefetch target this
        // step ((e+2) mod 6 differs from (e+4),(e+5) mod 6). Unconditional —
        // in the final step it reads valid-but-unused smem.
        mma_phase(acc, af[1], bf[1], af[0], bf[0],
                  aLane + s2, bLane + s2, offA0, offB0);

        // Complete stages e+3, e+4 (leave e+5 pending): next step's entry
        // invariant = stages e',e'+1,e'+2 complete, e'+3 pending.
        if (e + 5 < KSTEPS) {
            asm volatile("cp.async.wait_group 1;\n" ::);
        } else {
            asm volatile("cp.async.wait_group 0;\n" ::);
        }
        __syncthreads();
        sb0 = wrap6(sb0 + 2 * STAGE_BYTES);
    }

    // Epilogue
    #pragma unroll
    for (int mt = 0; mt < 2; ++mt) {
        const int rbase = m0 + wm + mt * 16 + qr;
        #pragma unroll
        for (int nt = 0; nt < 8; ++nt) {
            const int nbase = n0 + wn + nt * 8 + 2 * tg;
            const float b0 = bias[nbase];
            const float b1 = bias[nbase + 1];
            float2 v0 = make_float2(acc[mt][nt][0] + b0, acc[mt][nt][1] + b1);
            float2 v1 = make_float2(acc[mt][nt][2] + b0, acc[mt][nt][3] + b1);
            *(float2*)(out + (size_t)rbase * NROWS + nbase) = v0;
            *(float2*)(out + (size_t)(rbase + 8) * NROWS + nbase) = v1;
        }
    }
}

extern "C" void kernel_launch(void* const* d_in, const int* in_sizes, int n_in,
                              void* d_out, int out_size) {
    const float* x    = (const float*)d_in[0];
    const float* wval = (const float*)d_in[1];
    const float* bias = (const float*)d_in[2];
    const int*   rows = (const int*)d_in[3];
    const int*   cols = (const int*)d_in[4];
    float* out = (float*)d_out;

    prep_kernel<<<(XCHUNKS + NNZ_TOTAL + 255) / 256, 256>>>(x, wval, rows, cols);

    cudaFuncSetAttribute(sgemm_fp16,
                         cudaFuncAttributeMaxDynamicSharedMemorySize, SMEM_BYTES);
    dim3 grid(NROWS / BN, BATCH / BM);
    sgemm_fp16<<<grid, 256, SMEM_BYTES>>>(bias, out);
}